// round 2
// baseline (speedup 1.0000x reference)
#include <cuda_runtime.h>

#define CDIM 128
#define KTOT 1024
#define MV   128     // vectors per block
#define NT   128     // codes per tile
#define HW   4096    // H*W
#define ZP   132     // zsT pitch (multiple of 4 for float4, 132%32==4 avoids conflicts)

typedef unsigned long long ull;

// scratch (no allocations allowed)
__device__ float  g_enorm[KTOT];
__device__ int    g_used[KTOT];
__device__ double g_sq;

// smem: zsT[CDIM][ZP] + cs[NT][CDIM] + zn[MV] + se[NT]
#define SMEM_FLOATS (CDIM*ZP + NT*CDIM + MV + NT)
#define SMEM_BYTES  (SMEM_FLOATS * 4)

// ---- packed f32x2 helpers (two independent IEEE-rn fp32 FMAs / instr) ----
__device__ __forceinline__ void ffma2(ull& d, ull a, ull b, ull c) {
    asm("fma.rn.f32x2 %0, %1, %2, %3;" : "=l"(d) : "l"(a), "l"(b), "l"(c));
}
__device__ __forceinline__ ull dup2(float x) {
    ull r;
    asm("mov.b64 %0, {%1, %1};" : "=l"(r) : "f"(x));
    return r;
}
__device__ __forceinline__ void unpack2(ull v, float& lo, float& hi) {
    asm("mov.b64 {%0, %1}, %2;" : "=f"(lo), "=f"(hi) : "l"(v));
}

// ---------------------------------------------------------------------------
// Kernel 1: init — zero usage flags / MSE accumulator, precompute ||e_k||^2
// 32 blocks x 32 threads: one thread per codebook row, spread across SMs.
// ---------------------------------------------------------------------------
__global__ void vq_init(const float* __restrict__ cb) {
    int k = blockIdx.x * 32 + threadIdx.x;     // 0..1023
    g_used[k] = 0;
    if (k == 0) g_sq = 0.0;
    const float* row = cb + k * CDIM;
    float s = 0.f;
    #pragma unroll 8
    for (int c = 0; c < CDIM; ++c) s = __fmaf_rn(row[c], row[c], s);
    g_enorm[k] = s;
}

// ---------------------------------------------------------------------------
// Kernel 2: main — distance GEMM + argmin + gather epilogue + MSE partial
// ---------------------------------------------------------------------------
__global__ void __launch_bounds__(256, 1) vq_main(
    const float* __restrict__ z, const float* __restrict__ cb,
    float* __restrict__ out)
{
    extern __shared__ float sm[];
    float* zsT = sm;                    // [CDIM][ZP]   z tile, transposed
    float* cs  = sm + CDIM * ZP;        // [NT][CDIM]   codebook tile (row-major)
    float* zn  = cs + NT * CDIM;        // [MV]         ||z||^2 per vector
    float* se  = zn + MV;               // [NT]         ||e||^2 per tile code
    // overlays used after the K loop (cs region is free then):
    float* rbest = cs;                  // [MV][17]
    int*   rki   = (int*)(cs + MV * 17);// [MV][17]

    const int tid = threadIdx.x;
    const int n0  = blockIdx.x * MV;
    const int b   = n0 >> 12;           // n0 / HW
    const int p0  = n0 & (HW - 1);
    const float* zbase = z + (size_t)b * CDIM * HW + p0;

    // ---- stage z: (coalesced float4 reads, conflict-free STS) ----
    #pragma unroll
    for (int it = 0; it < 16; ++it) {
        int idx = it * 256 + tid;                 // 0..4095 float4 slots
        int c   = idx >> 5;
        int vv  = (idx & 31) << 2;
        float4 val = *reinterpret_cast<const float4*>(zbase + (size_t)c * HW + vv);
        float* dst = zsT + c * ZP + vv;
        dst[0] = val.x; dst[1] = val.y; dst[2] = val.z; dst[3] = val.w;
    }
    __syncthreads();

    // ---- ||z||^2 per vector (sequential ascending c, IEEE fma) ----
    if (tid < MV) {
        float s = 0.f;
        #pragma unroll 8
        for (int c = 0; c < CDIM; ++c) {
            float x = zsT[c * ZP + tid];
            s = __fmaf_rn(x, x, s);
        }
        zn[tid] = s;
    }
    __syncthreads();

    const int v4 = (tid & 15) << 2;     // vector group base (covers v4..v4+3, v4+64..v4+67)
    const int k4 = (tid >> 4) << 2;     // code group base   (covers k4..k4+3, k4+64..k4+67)

    float vnr[8];
    #pragma unroll
    for (int i = 0; i < 8; ++i) vnr[i] = zn[v4 + (i < 4 ? i : 60 + i)];

    float best[8]; int bestk[8];
    #pragma unroll
    for (int i = 0; i < 8; ++i) { best[i] = 3.4e38f; bestk[i] = 0; }

    for (int kt = 0; kt < KTOT / NT; ++kt) {
        // ---- stage codebook tile (fully coalesced, conflict-free) ----
        const float* cbt = cb + (size_t)kt * NT * CDIM;
        #pragma unroll
        for (int it = 0; it < 16; ++it) {
            int idx = it * 256 + tid;
            int k   = idx >> 5;
            int c4  = (idx & 31) << 2;
            float4 val = *reinterpret_cast<const float4*>(cbt + k * CDIM + c4);
            *reinterpret_cast<float4*>(cs + k * CDIM + c4) = val;
        }
        if (tid < NT) se[tid] = g_enorm[kt * NT + tid];
        __syncthreads();

        // ---- 8x8 register micro-tile GEMM over C, packed f32x2 along v ----
        // acc2[i][j]: i = v-pair (v4+2i / v4+64+2(i-2)), j = code k4+j / k4+60+j
        ull acc2[4][8];
        #pragma unroll
        for (int i = 0; i < 4; ++i)
            #pragma unroll
            for (int j = 0; j < 8; ++j) acc2[i][j] = 0ull;

        #pragma unroll 4
        for (int c = 0; c < CDIM; ++c) {
            // A operand: 4 packed v-pairs, straight from LDS.128 (no pack movs)
            ulonglong2 a01 = *reinterpret_cast<const ulonglong2*>(zsT + c * ZP + v4);
            ulonglong2 a23 = *reinterpret_cast<const ulonglong2*>(zsT + c * ZP + v4 + 64);
            ull ap[4] = {a01.x, a01.y, a23.x, a23.y};
            // B operand: 8 scalar loads, duplicated into both packed lanes
            ull bb[8];
            #pragma unroll
            for (int j = 0; j < 4; ++j) bb[j]     = dup2(cs[(k4 + j) * CDIM + c]);
            #pragma unroll
            for (int j = 0; j < 4; ++j) bb[4 + j] = dup2(cs[(k4 + 64 + j) * CDIM + c]);
            #pragma unroll
            for (int i = 0; i < 4; ++i)
                #pragma unroll
                for (int j = 0; j < 8; ++j)
                    ffma2(acc2[i][j], ap[i], bb[j], acc2[i][j]);
        }

        // ---- scores + running argmin (reference formula & rounding) ----
        #pragma unroll
        for (int j = 0; j < 8; ++j) {
            int kl = (j < 4) ? (k4 + j) : (k4 + 60 + j);   // ascending within thread
            float ek = se[kl];
            int   kg = kt * NT + kl;
            #pragma unroll
            for (int i = 0; i < 4; ++i) {
                float dot_lo, dot_hi;
                unpack2(acc2[i][j], dot_lo, dot_hi);
                int m = 2 * i;     // best[] index of the lo lane; hi lane is m+1
                // d = fl( fl(znorm + enorm) - fl(2 * dot) )  — matches jnp expression
                float d0 = __fsub_rn(__fadd_rn(vnr[m],     ek), __fmul_rn(2.0f, dot_lo));
                float d1 = __fsub_rn(__fadd_rn(vnr[m + 1], ek), __fmul_rn(2.0f, dot_hi));
                if (d0 < best[m])     { best[m]     = d0; bestk[m]     = kg; }
                if (d1 < best[m + 1]) { best[m + 1] = d1; bestk[m + 1] = kg; }
            }
        }
        __syncthreads();   // before overwriting cs/se next tile
    }

    // ---- cross-thread argmin reduction (lexicographic: score, then index) ----
    int g = tid >> 4;
    #pragma unroll
    for (int i = 0; i < 8; ++i) {
        int v = v4 + (i < 4 ? i : 60 + i);
        rbest[v * 17 + g] = best[i];
        rki  [v * 17 + g] = bestk[i];
    }
    __syncthreads();

    float errsum = 0.f;
    if (tid < MV) {
        int v = tid;
        float bb = rbest[v * 17]; int bk = rki[v * 17];
        #pragma unroll
        for (int gg = 1; gg < 16; ++gg) {
            float nb = rbest[v * 17 + gg];
            int   nk = rki  [v * 17 + gg];
            if (nb < bb || (nb == bb && nk < bk)) { bb = nb; bk = nk; }
        }
        g_used[bk] = 1;

        // epilogue: z_q_st = fl(z + fl(z_q - z)) written in (B,C,H,W); MSE partial
        const float4* crow = reinterpret_cast<const float4*>(cb + (size_t)bk * CDIM);
        float* ob = out + (size_t)b * CDIM * HW + p0 + v;
        #pragma unroll 8
        for (int c4 = 0; c4 < 32; ++c4) {
            float4 e4 = crow[c4];
            float ee[4] = {e4.x, e4.y, e4.z, e4.w};
            #pragma unroll
            for (int jj = 0; jj < 4; ++jj) {
                int c = c4 * 4 + jj;
                float zv = zsT[c * ZP + v];
                float t  = __fsub_rn(ee[jj], zv);          // z_q - z
                ob[(size_t)c * HW] = __fadd_rn(zv, t);     // straight-through value
                errsum = __fmaf_rn(t, t, errsum);
            }
        }
    }

    // ---- block reduction of squared error -> double atomic ----
    float* sred = zn;   // zn no longer needed
    __syncthreads();
    if (tid < MV) sred[tid] = errsum;
    __syncthreads();
    if (tid < 64) sred[tid] = __fadd_rn(sred[tid], sred[tid + 64]);
    __syncthreads();
    if (tid < 32) {
        float s = __fadd_rn(sred[tid], sred[tid + 32]);
        #pragma unroll
        for (int off = 16; off; off >>= 1)
            s = __fadd_rn(s, __shfl_down_sync(0xffffffffu, s, off));
        if (tid == 0) atomicAdd(&g_sq, (double)s);
    }
}

// ---------------------------------------------------------------------------
// Kernel 3: finalize — vq_loss + usage scalars
// ---------------------------------------------------------------------------
__global__ void vq_fin(float* __restrict__ out, int npix) {
    __shared__ int cnt[32];
    int tid = threadIdx.x;             // 1024 threads
    int u = g_used[tid] ? 1 : 0;
    #pragma unroll
    for (int off = 16; off; off >>= 1) u += __shfl_down_sync(0xffffffffu, u, off);
    if ((tid & 31) == 0) cnt[tid >> 5] = u;
    __syncthreads();
    if (tid == 0) {
        int total = 0;
        #pragma unroll
        for (int i = 0; i < 32; ++i) total += cnt[i];
        float m  = (float)(g_sq / (double)npix);
        // vq_loss = codebook_loss + 0.25 * commitment_loss (identical forward values)
        float vq = __fadd_rn(m, __fmul_rn(0.25f, m));
        out[npix]     = vq;
        out[npix + 1] = (float)total * (1.0f / 1024.0f);  // exact /1024
    }
}

// ---------------------------------------------------------------------------
extern "C" void kernel_launch(void* const* d_in, const int* in_sizes, int n_in,
                              void* d_out, int out_size) {
    const float* z  = (const float*)d_in[0];
    const float* cb = (const float*)d_in[1];
    float* out = (float*)d_out;
    int npix = out_size - 2;                    // 8388608
    int nvec = npix / CDIM;                     // 65536
    int blocks = nvec / MV;                     // 512

    cudaFuncSetAttribute(vq_main, cudaFuncAttributeMaxDynamicSharedMemorySize, SMEM_BYTES);

    vq_init<<<32, 32>>>(cb);
    vq_main<<<blocks, 256, SMEM_BYTES>>>(z, cb, out);
    vq_fin<<<1, KTOT>>>(out, npix);
}

// round 3
// speedup vs baseline: 1.4524x; 1.4524x over previous
#include <cuda_runtime.h>

#define CDIM 128
#define KTOT 1024
#define MV   128     // vectors per block
#define NT   128     // codes per tile
#define HW   4096    // H*W
#define ZP   132     // zsT pitch (multiple of 4 for float4, 132%32==4 avoids conflicts)

// scratch (no allocations allowed)
__device__ float  g_enorm[KTOT];
__device__ int    g_used[KTOT];
__device__ double g_sq;

// smem: zsT[CDIM][ZP] + cs[NT][CDIM] + zn[MV] + se[NT]
#define SMEM_FLOATS (CDIM*ZP + NT*CDIM + MV + NT)
#define SMEM_BYTES  (SMEM_FLOATS * 4)

// ---------------------------------------------------------------------------
// Kernel 1: init — zero usage flags / MSE accumulator, precompute ||e_k||^2
// 128 blocks x 8 threads: one thread per codebook row, spread across SMs.
// Sequential ascending-c FMA chain (must match reference-compatible rounding).
// ---------------------------------------------------------------------------
__global__ void vq_init(const float* __restrict__ cb) {
    int k = blockIdx.x * 8 + threadIdx.x;      // 0..1023
    g_used[k] = 0;
    if (k == 0) g_sq = 0.0;
    const float* row = cb + k * CDIM;
    float s = 0.f;
    #pragma unroll 8
    for (int c = 0; c < CDIM; ++c) s = __fmaf_rn(row[c], row[c], s);
    g_enorm[k] = s;
}

// ---------------------------------------------------------------------------
// Kernel 2: main — distance GEMM + argmin + gather epilogue + MSE partial
// ---------------------------------------------------------------------------
__global__ void __launch_bounds__(256, 1) vq_main(
    const float* __restrict__ z, const float* __restrict__ cb,
    float* __restrict__ out)
{
    extern __shared__ float sm[];
    float* zsT = sm;                    // [CDIM][ZP]   z tile, transposed
    float* cs  = sm + CDIM * ZP;        // [NT][CDIM]   codebook tile (row-major)
    float* zn  = cs + NT * CDIM;        // [MV]         ||z||^2 per vector
    float* se  = zn + MV;               // [NT]         ||e||^2 per tile code
    // overlays used after the K loop (cs region is free then):
    float* rbest = cs;                  // [MV][17]
    int*   rki   = (int*)(cs + MV * 17);// [MV][17]

    const int tid = threadIdx.x;
    const int n0  = blockIdx.x * MV;
    const int b   = n0 >> 12;           // n0 / HW
    const int p0  = n0 & (HW - 1);
    const float* zbase = z + (size_t)b * CDIM * HW + p0;

    // ---- stage z: (coalesced float4 reads, conflict-free STS) ----
    #pragma unroll
    for (int it = 0; it < 16; ++it) {
        int idx = it * 256 + tid;                 // 0..4095 float4 slots
        int c   = idx >> 5;
        int vv  = (idx & 31) << 2;
        float4 val = *reinterpret_cast<const float4*>(zbase + (size_t)c * HW + vv);
        float* dst = zsT + c * ZP + vv;
        dst[0] = val.x; dst[1] = val.y; dst[2] = val.z; dst[3] = val.w;
    }
    __syncthreads();

    // ---- ||z||^2 per vector (sequential ascending c, IEEE fma) ----
    if (tid < MV) {
        float s = 0.f;
        #pragma unroll 8
        for (int c = 0; c < CDIM; ++c) {
            float x = zsT[c * ZP + tid];
            s = __fmaf_rn(x, x, s);
        }
        zn[tid] = s;
    }
    __syncthreads();

    const int v4 = (tid & 15) << 2;     // vector group base (covers v4..v4+3, v4+64..v4+67)
    const int k4 = (tid >> 4) << 2;     // code group base   (covers k4..k4+3, k4+64..k4+67)

    float vnr[8];
    #pragma unroll
    for (int i = 0; i < 8; ++i) vnr[i] = zn[v4 + (i < 4 ? i : 60 + i)];

    float best[8]; int bestk[8];
    #pragma unroll
    for (int i = 0; i < 8; ++i) { best[i] = 3.4e38f; bestk[i] = 0; }

    for (int kt = 0; kt < KTOT / NT; ++kt) {
        // ---- stage codebook tile (fully coalesced, conflict-free) ----
        const float* cbt = cb + (size_t)kt * NT * CDIM;
        #pragma unroll
        for (int it = 0; it < 16; ++it) {
            int idx = it * 256 + tid;
            int k   = idx >> 5;
            int c4s = (idx & 31) << 2;
            float4 val = *reinterpret_cast<const float4*>(cbt + k * CDIM + c4s);
            *reinterpret_cast<float4*>(cs + k * CDIM + c4s) = val;
        }
        if (tid < NT) se[tid] = g_enorm[kt * NT + tid];
        __syncthreads();

        // ---- 8x8 register micro-tile GEMM over C, processed in 4-c chunks ----
        // A: LDS.128 along v (zsT),  B: LDS.128 along c (cs row-major).
        // Accumulation order per (v,k) stays strictly ascending in c.
        float acc[8][8];
        #pragma unroll
        for (int i = 0; i < 8; ++i)
            #pragma unroll
            for (int j = 0; j < 8; ++j) acc[i][j] = 0.f;

        #pragma unroll 1
        for (int c4 = 0; c4 < CDIM; c4 += 4) {
            float4 a0[4], a1[4];
            #pragma unroll
            for (int i = 0; i < 4; ++i) {
                a0[i] = *reinterpret_cast<const float4*>(zsT + (c4 + i) * ZP + v4);
                a1[i] = *reinterpret_cast<const float4*>(zsT + (c4 + i) * ZP + v4 + 64);
            }
            float4 bq[8];
            #pragma unroll
            for (int j = 0; j < 4; ++j)
                bq[j]     = *reinterpret_cast<const float4*>(cs + (k4 + j) * CDIM + c4);
            #pragma unroll
            for (int j = 0; j < 4; ++j)
                bq[4 + j] = *reinterpret_cast<const float4*>(cs + (k4 + 64 + j) * CDIM + c4);

            #pragma unroll
            for (int cc = 0; cc < 4; ++cc) {     // ascending c within chunk
                float av[8];
                av[0] = (&a0[cc].x)[0]; av[1] = (&a0[cc].x)[1];
                av[2] = (&a0[cc].x)[2]; av[3] = (&a0[cc].x)[3];
                av[4] = (&a1[cc].x)[0]; av[5] = (&a1[cc].x)[1];
                av[6] = (&a1[cc].x)[2]; av[7] = (&a1[cc].x)[3];
                #pragma unroll
                for (int j = 0; j < 8; ++j) {
                    float bv = (&bq[j].x)[cc];
                    #pragma unroll
                    for (int i = 0; i < 8; ++i)
                        acc[i][j] = __fmaf_rn(av[i], bv, acc[i][j]);
                }
            }
        }

        // ---- scores + running argmin (reference formula & rounding) ----
        #pragma unroll
        for (int j = 0; j < 8; ++j) {
            int kl = (j < 4) ? (k4 + j) : (k4 + 60 + j);   // ascending within thread
            float ek = se[kl];
            int   kg = kt * NT + kl;
            #pragma unroll
            for (int i = 0; i < 8; ++i) {
                // d = fl( fl(znorm + enorm) - fl(2 * dot) )  — matches jnp expression
                float d = __fsub_rn(__fadd_rn(vnr[i], ek), __fmul_rn(2.0f, acc[i][j]));
                if (d < best[i]) { best[i] = d; bestk[i] = kg; }  // strict <: first idx wins
            }
        }
        __syncthreads();   // before overwriting cs/se next tile
    }

    // ---- cross-thread argmin reduction (lexicographic: score, then index) ----
    int g = tid >> 4;
    #pragma unroll
    for (int i = 0; i < 8; ++i) {
        int v = v4 + (i < 4 ? i : 60 + i);
        rbest[v * 17 + g] = best[i];
        rki  [v * 17 + g] = bestk[i];
    }
    __syncthreads();

    float errsum = 0.f;
    if (tid < MV) {
        int v = tid;
        float bb = rbest[v * 17]; int bk = rki[v * 17];
        #pragma unroll
        for (int gg = 1; gg < 16; ++gg) {
            float nb = rbest[v * 17 + gg];
            int   nk = rki  [v * 17 + gg];
            if (nb < bb || (nb == bb && nk < bk)) { bb = nb; bk = nk; }
        }
        g_used[bk] = 1;

        // epilogue: z_q_st = fl(z + fl(z_q - z)) written in (B,C,H,W); MSE partial
        const float4* crow = reinterpret_cast<const float4*>(cb + (size_t)bk * CDIM);
        float* ob = out + (size_t)b * CDIM * HW + p0 + v;
        #pragma unroll 8
        for (int c4 = 0; c4 < 32; ++c4) {
            float4 e4 = crow[c4];
            float ee[4] = {e4.x, e4.y, e4.z, e4.w};
            #pragma unroll
            for (int jj = 0; jj < 4; ++jj) {
                int c = c4 * 4 + jj;
                float zv = zsT[c * ZP + v];
                float t  = __fsub_rn(ee[jj], zv);          // z_q - z
                ob[(size_t)c * HW] = __fadd_rn(zv, t);     // straight-through value
                errsum = __fmaf_rn(t, t, errsum);
            }
        }
    }

    // ---- block reduction of squared error -> double atomic ----
    float* sred = zn;   // zn no longer needed
    __syncthreads();
    if (tid < MV) sred[tid] = errsum;
    __syncthreads();
    if (tid < 64) sred[tid] = __fadd_rn(sred[tid], sred[tid + 64]);
    __syncthreads();
    if (tid < 32) {
        float s = __fadd_rn(sred[tid], sred[tid + 32]);
        #pragma unroll
        for (int off = 16; off; off >>= 1)
            s = __fadd_rn(s, __shfl_down_sync(0xffffffffu, s, off));
        if (tid == 0) atomicAdd(&g_sq, (double)s);
    }
}

// ---------------------------------------------------------------------------
// Kernel 3: finalize — vq_loss + usage scalars
// ---------------------------------------------------------------------------
__global__ void vq_fin(float* __restrict__ out, int npix) {
    __shared__ int cnt[32];
    int tid = threadIdx.x;             // 1024 threads
    int u = g_used[tid] ? 1 : 0;
    #pragma unroll
    for (int off = 16; off; off >>= 1) u += __shfl_down_sync(0xffffffffu, u, off);
    if ((tid & 31) == 0) cnt[tid >> 5] = u;
    __syncthreads();
    if (tid == 0) {
        int total = 0;
        #pragma unroll
        for (int i = 0; i < 32; ++i) total += cnt[i];
        float m  = (float)(g_sq / (double)npix);
        // vq_loss = codebook_loss + 0.25 * commitment_loss (identical forward values)
        float vq = __fadd_rn(m, __fmul_rn(0.25f, m));
        out[npix]     = vq;
        out[npix + 1] = (float)total * (1.0f / 1024.0f);  // exact /1024
    }
}

// ---------------------------------------------------------------------------
extern "C" void kernel_launch(void* const* d_in, const int* in_sizes, int n_in,
                              void* d_out, int out_size) {
    const float* z  = (const float*)d_in[0];
    const float* cb = (const float*)d_in[1];
    float* out = (float*)d_out;
    int npix = out_size - 2;                    // 8388608
    int nvec = npix / CDIM;                     // 65536
    int blocks = nvec / MV;                     // 512

    cudaFuncSetAttribute(vq_main, cudaFuncAttributeMaxDynamicSharedMemorySize, SMEM_BYTES);

    vq_init<<<128, 8>>>(cb);
    vq_main<<<blocks, 256, SMEM_BYTES>>>(z, cb, out);
    vq_fin<<<1, KTOT>>>(out, npix);
}